// round 1
// baseline (speedup 1.0000x reference)
#include <cuda_runtime.h>
#include <cuda_bf16.h>
#include <math.h>

#define BB 2
#define SS 2048
#define HH 16
#define DHD 128
#define HIDD 2048
#define NQKV 6144   // (H + 2*HKV) * DH

// ---------------- scratch (static device allocations — allowed) ----------------
__device__ float g_qkv[(size_t)BB * SS * NQKV];         // [4096, 6144]
__device__ float g_q[(size_t)BB * HH * SS * DHD];       // [bh, s, d] (pre-scaled by 1/sqrt(DH))
__device__ float g_k[(size_t)BB * HH * SS * DHD];
__device__ float g_v[(size_t)BB * HH * SS * DHD];
__device__ float g_attn[(size_t)BB * SS * HH * DHD];    // [b, s, h, d] == [4096, 2048]

// ---------------- helpers ----------------
__device__ __forceinline__ unsigned f2tf(float f) {
    unsigned u;
    asm("cvt.rna.tf32.f32 %0, %1;" : "=r"(u) : "f"(f));
    return u;
}

__device__ __forceinline__ void mma_tf32(float (&c)[4],
                                         unsigned a0, unsigned a1, unsigned a2, unsigned a3,
                                         unsigned b0, unsigned b1) {
    asm volatile(
        "mma.sync.aligned.m16n8k8.row.col.f32.tf32.tf32.f32 "
        "{%0,%1,%2,%3},{%4,%5,%6,%7},{%8,%9},{%0,%1,%2,%3};\n"
        : "+f"(c[0]), "+f"(c[1]), "+f"(c[2]), "+f"(c[3])
        : "r"(a0), "r"(a1), "r"(a2), "r"(a3), "r"(b0), "r"(b1));
}

// ---------------- GEMM: C[M,N] = A[M,K] * B[N,K]^T (both row-major, K-contig) ----------------
// Block 128x128, BK=16, 256 threads, 8 warps each 64x32. Double-buffered smem.
__global__ __launch_bounds__(256, 2) void gemm_nt(const float* __restrict__ A,
                                                  const float* __restrict__ Bm,
                                                  float* __restrict__ C,
                                                  int M, int N, int K) {
    __shared__ unsigned sA[2][128 * 20];
    __shared__ unsigned sB[2][128 * 20];

    const int tid = threadIdx.x;
    const int lane = tid & 31;
    const int w = tid >> 5;
    const int g = lane >> 2;
    const int tg = lane & 3;
    const int wrow = (w >> 2) * 64;
    const int wcol = (w & 3) * 32;
    const int bm = blockIdx.y * 128;
    const int bn = blockIdx.x * 128;
    const int nk = K >> 4;

    float acc[4][4][4];
#pragma unroll
    for (int i = 0; i < 4; i++)
#pragma unroll
        for (int j = 0; j < 4; j++)
#pragma unroll
            for (int l = 0; l < 4; l++) acc[i][j][l] = 0.f;

    const int r0 = tid >> 2, c0 = (tid & 3) * 4;
    const int r1 = (tid + 256) >> 2, c1 = ((tid + 256) & 3) * 4;
    const float* Ap0 = A + (size_t)(bm + r0) * K + c0;
    const float* Ap1 = A + (size_t)(bm + r1) * K + c1;
    const float* Bp0 = Bm + (size_t)(bn + r0) * K + c0;
    const float* Bp1 = Bm + (size_t)(bn + r1) * K + c1;

    float4 ra0 = *(const float4*)Ap0;
    float4 ra1 = *(const float4*)Ap1;
    float4 rb0 = *(const float4*)Bp0;
    float4 rb1 = *(const float4*)Bp1;
    {
        unsigned* d;
        d = &sA[0][r0 * 20 + c0]; d[0] = f2tf(ra0.x); d[1] = f2tf(ra0.y); d[2] = f2tf(ra0.z); d[3] = f2tf(ra0.w);
        d = &sA[0][r1 * 20 + c1]; d[0] = f2tf(ra1.x); d[1] = f2tf(ra1.y); d[2] = f2tf(ra1.z); d[3] = f2tf(ra1.w);
        d = &sB[0][r0 * 20 + c0]; d[0] = f2tf(rb0.x); d[1] = f2tf(rb0.y); d[2] = f2tf(rb0.z); d[3] = f2tf(rb0.w);
        d = &sB[0][r1 * 20 + c1]; d[0] = f2tf(rb1.x); d[1] = f2tf(rb1.y); d[2] = f2tf(rb1.z); d[3] = f2tf(rb1.w);
    }
    __syncthreads();

    for (int kt = 0; kt < nk; kt++) {
        const int cur = kt & 1;
        if (kt + 1 < nk) {
            ra0 = *(const float4*)(Ap0 + (kt + 1) * 16);
            ra1 = *(const float4*)(Ap1 + (kt + 1) * 16);
            rb0 = *(const float4*)(Bp0 + (kt + 1) * 16);
            rb1 = *(const float4*)(Bp1 + (kt + 1) * 16);
        }
        const unsigned* sa = sA[cur];
        const unsigned* sb = sB[cur];
#pragma unroll
        for (int ks = 0; ks < 2; ks++) {
            unsigned af[4][4], bf[4][2];
#pragma unroll
            for (int mt = 0; mt < 4; mt++) {
                int rr = wrow + mt * 16;
                af[mt][0] = sa[(rr + g) * 20 + ks * 8 + tg];
                af[mt][1] = sa[(rr + g + 8) * 20 + ks * 8 + tg];
                af[mt][2] = sa[(rr + g) * 20 + ks * 8 + tg + 4];
                af[mt][3] = sa[(rr + g + 8) * 20 + ks * 8 + tg + 4];
            }
#pragma unroll
            for (int nt = 0; nt < 4; nt++) {
                int nn = wcol + nt * 8;
                bf[nt][0] = sb[(nn + g) * 20 + ks * 8 + tg];
                bf[nt][1] = sb[(nn + g) * 20 + ks * 8 + tg + 4];
            }
#pragma unroll
            for (int mt = 0; mt < 4; mt++)
#pragma unroll
                for (int nt = 0; nt < 4; nt++)
                    mma_tf32(acc[mt][nt], af[mt][0], af[mt][1], af[mt][2], af[mt][3],
                             bf[nt][0], bf[nt][1]);
        }
        if (kt + 1 < nk) {
            const int nxt = cur ^ 1;
            unsigned* d;
            d = &sA[nxt][r0 * 20 + c0]; d[0] = f2tf(ra0.x); d[1] = f2tf(ra0.y); d[2] = f2tf(ra0.z); d[3] = f2tf(ra0.w);
            d = &sA[nxt][r1 * 20 + c1]; d[0] = f2tf(ra1.x); d[1] = f2tf(ra1.y); d[2] = f2tf(ra1.z); d[3] = f2tf(ra1.w);
            d = &sB[nxt][r0 * 20 + c0]; d[0] = f2tf(rb0.x); d[1] = f2tf(rb0.y); d[2] = f2tf(rb0.z); d[3] = f2tf(rb0.w);
            d = &sB[nxt][r1 * 20 + c1]; d[0] = f2tf(rb1.x); d[1] = f2tf(rb1.y); d[2] = f2tf(rb1.z); d[3] = f2tf(rb1.w);
        }
        __syncthreads();
    }

#pragma unroll
    for (int mt = 0; mt < 4; mt++) {
        int rr = bm + wrow + mt * 16 + g;
#pragma unroll
        for (int nt = 0; nt < 4; nt++) {
            int cc = bn + wcol + nt * 8 + 2 * tg;
            *(float2*)&C[(size_t)rr * N + cc] = make_float2(acc[mt][nt][0], acc[mt][nt][1]);
            *(float2*)&C[(size_t)(rr + 8) * N + cc] = make_float2(acc[mt][nt][2], acc[mt][nt][3]);
        }
    }
}

// ---------------- RoPE + split + transpose to head-major ----------------
// out[2i]   = x[2i]*cos - x[2i+1]*sin ;  out[2i+1] = x[2i+1]*cos + x[2i]*sin
// (cos/sin repeated pairs: cos[2i]==cos[2i+1]).  Q additionally scaled by 1/sqrt(DH).
__global__ void rope_split_kernel(const float* __restrict__ cosb, const float* __restrict__ sinb) {
    int idx = blockIdx.x * blockDim.x + threadIdx.x;  // pair index, exact grid
    int m = idx / 3072;
    int p = idx - m * 3072;
    int o = p * 2;
    int head = o >> 7;
    int d = o & 127;
    int b = m >> 11;
    int s = m & 2047;
    float2 x = *(const float2*)(g_qkv + (size_t)m * NQKV + o);
    if (head < 2 * HH) {
        float c = cosb[s * DHD + d];
        float sn = sinb[s * DHD + d];
        float y0 = x.x * c - x.y * sn;
        float y1 = x.y * c + x.x * sn;
        if (head < HH) {
            const float sc = 0.08838834764831845f;  // 1/sqrt(128)
            float* dst = g_q + (((size_t)(b * HH + head)) * SS + s) * DHD + d;
            *(float2*)dst = make_float2(y0 * sc, y1 * sc);
        } else {
            float* dst = g_k + (((size_t)(b * HH + head - HH)) * SS + s) * DHD + d;
            *(float2*)dst = make_float2(y0, y1);
        }
    } else {
        float* dst = g_v + (((size_t)(b * HH + head - 2 * HH)) * SS + s) * DHD + d;
        *(float2*)dst = x;
    }
}

// ---------------- Flash attention ----------------
// Grid: (S/128, B*H). 256 threads = 8 warps, each warp owns 16 q-rows.
// smem (uints): Q[128][132], K[64][132], V[64][136], P[128][68]  -> 171008 bytes
#define FA_SMEM_BYTES 171008

__global__ __launch_bounds__(256, 1) void flash_kernel() {
    extern __shared__ unsigned fsm[];
    unsigned* sQ = fsm;                // 128*132 = 16896
    unsigned* sK = fsm + 16896;        // 64*132  =  8448
    unsigned* sV = fsm + 25344;        // 64*136  =  8704
    unsigned* sP = fsm + 34048;        // 128*68  =  8704

    const int tid = threadIdx.x;
    const int lane = tid & 31;
    const int w = tid >> 5;
    const int g = lane >> 2;
    const int tg = lane & 3;
    const int qt = blockIdx.x;
    const int bh = blockIdx.y;
    const int qrow = w * 16;

    const float* qp = g_q + ((size_t)bh * SS + qt * 128) * DHD;
#pragma unroll
    for (int i = 0; i < 16; i++) {
        int id = tid + 256 * i;
        int r = id >> 5, c4 = (id & 31) * 4;
        float4 v = *(const float4*)(qp + (size_t)r * DHD + c4);
        unsigned* d = sQ + r * 132 + c4;
        d[0] = f2tf(v.x); d[1] = f2tf(v.y); d[2] = f2tf(v.z); d[3] = f2tf(v.w);
    }

    float m0 = -1e30f, m1 = -1e30f, l0 = 0.f, l1 = 0.f;
    float oacc[16][4];
#pragma unroll
    for (int nt = 0; nt < 16; nt++) { oacc[nt][0] = 0; oacc[nt][1] = 0; oacc[nt][2] = 0; oacc[nt][3] = 0; }

    for (int kt = 0; kt < SS / 64; kt++) {
        const float* kp = g_k + ((size_t)bh * SS + kt * 64) * DHD;
        const float* vp = g_v + ((size_t)bh * SS + kt * 64) * DHD;
#pragma unroll
        for (int i = 0; i < 8; i++) {
            int id = tid + 256 * i;
            int r = id >> 5, c4 = (id & 31) * 4;
            float4 kv = *(const float4*)(kp + (size_t)r * DHD + c4);
            unsigned* dk = sK + r * 132 + c4;
            dk[0] = f2tf(kv.x); dk[1] = f2tf(kv.y); dk[2] = f2tf(kv.z); dk[3] = f2tf(kv.w);
            float4 vv = *(const float4*)(vp + (size_t)r * DHD + c4);
            unsigned* dv = sV + r * 136 + c4;
            dv[0] = f2tf(vv.x); dv[1] = f2tf(vv.y); dv[2] = f2tf(vv.z); dv[3] = f2tf(vv.w);
        }
        __syncthreads();

        // S = Q K^T  (scale already folded into Q)
        float sacc[8][4];
#pragma unroll
        for (int nt = 0; nt < 8; nt++) { sacc[nt][0] = 0; sacc[nt][1] = 0; sacc[nt][2] = 0; sacc[nt][3] = 0; }
#pragma unroll
        for (int ks = 0; ks < 16; ks++) {
            unsigned a0 = sQ[(qrow + g) * 132 + ks * 8 + tg];
            unsigned a1 = sQ[(qrow + g + 8) * 132 + ks * 8 + tg];
            unsigned a2 = sQ[(qrow + g) * 132 + ks * 8 + tg + 4];
            unsigned a3 = sQ[(qrow + g + 8) * 132 + ks * 8 + tg + 4];
#pragma unroll
            for (int nt = 0; nt < 8; nt++) {
                unsigned b0 = sK[(nt * 8 + g) * 132 + ks * 8 + tg];
                unsigned b1 = sK[(nt * 8 + g) * 132 + ks * 8 + tg + 4];
                mma_tf32(sacc[nt], a0, a1, a2, a3, b0, b1);
            }
        }

        // online softmax (rows g and g+8 of this warp's 16)
        float mx0 = sacc[0][0], mx1 = sacc[0][2];
#pragma unroll
        for (int nt = 0; nt < 8; nt++) {
            mx0 = fmaxf(mx0, fmaxf(sacc[nt][0], sacc[nt][1]));
            mx1 = fmaxf(mx1, fmaxf(sacc[nt][2], sacc[nt][3]));
        }
        mx0 = fmaxf(mx0, __shfl_xor_sync(0xffffffffu, mx0, 1));
        mx0 = fmaxf(mx0, __shfl_xor_sync(0xffffffffu, mx0, 2));
        mx1 = fmaxf(mx1, __shfl_xor_sync(0xffffffffu, mx1, 1));
        mx1 = fmaxf(mx1, __shfl_xor_sync(0xffffffffu, mx1, 2));
        float nm0 = fmaxf(m0, mx0), nm1 = fmaxf(m1, mx1);
        float al0 = __expf(m0 - nm0), al1 = __expf(m1 - nm1);
        float sum0 = 0.f, sum1 = 0.f;
        unsigned* pr0 = sP + (qrow + g) * 68;
        unsigned* pr1 = sP + (qrow + g + 8) * 68;
#pragma unroll
        for (int nt = 0; nt < 8; nt++) {
            int cc = nt * 8 + 2 * tg;
            unsigned u00 = f2tf(__expf(sacc[nt][0] - nm0));
            unsigned u01 = f2tf(__expf(sacc[nt][1] - nm0));
            unsigned u10 = f2tf(__expf(sacc[nt][2] - nm1));
            unsigned u11 = f2tf(__expf(sacc[nt][3] - nm1));
            sum0 += __uint_as_float(u00) + __uint_as_float(u01);  // sum the tf32-rounded P
            sum1 += __uint_as_float(u10) + __uint_as_float(u11);
            pr0[cc] = u00; pr0[cc + 1] = u01;
            pr1[cc] = u10; pr1[cc + 1] = u11;
        }
        sum0 += __shfl_xor_sync(0xffffffffu, sum0, 1);
        sum0 += __shfl_xor_sync(0xffffffffu, sum0, 2);
        sum1 += __shfl_xor_sync(0xffffffffu, sum1, 1);
        sum1 += __shfl_xor_sync(0xffffffffu, sum1, 2);
        l0 = l0 * al0 + sum0;
        l1 = l1 * al1 + sum1;
        m0 = nm0; m1 = nm1;
#pragma unroll
        for (int nt = 0; nt < 16; nt++) {
            oacc[nt][0] *= al0; oacc[nt][1] *= al0;
            oacc[nt][2] *= al1; oacc[nt][3] *= al1;
        }
        __syncwarp();

        // O += P V   (P is A-operand via smem, V is B-operand)
#pragma unroll
        for (int ks = 0; ks < 8; ks++) {
            unsigned a0 = sP[(qrow + g) * 68 + ks * 8 + tg];
            unsigned a1 = sP[(qrow + g + 8) * 68 + ks * 8 + tg];
            unsigned a2 = sP[(qrow + g) * 68 + ks * 8 + tg + 4];
            unsigned a3 = sP[(qrow + g + 8) * 68 + ks * 8 + tg + 4];
#pragma unroll
            for (int nt = 0; nt < 16; nt++) {
                unsigned b0 = sV[(ks * 8 + tg) * 136 + nt * 8 + g];
                unsigned b1 = sV[(ks * 8 + tg + 4) * 136 + nt * 8 + g];
                mma_tf32(oacc[nt], a0, a1, a2, a3, b0, b1);
            }
        }
        __syncthreads();
    }

    float inv0 = 1.0f / l0, inv1 = 1.0f / l1;
    int b = bh >> 4, h = bh & 15;
    int srow = qt * 128 + qrow + g;
    float* op0 = g_attn + (((size_t)b * SS + srow) * HH + h) * DHD;
    float* op1 = op0 + (size_t)8 * HH * DHD;
#pragma unroll
    for (int nt = 0; nt < 16; nt++) {
        int cc = nt * 8 + 2 * tg;
        *(float2*)(op0 + cc) = make_float2(oacc[nt][0] * inv0, oacc[nt][1] * inv0);
        *(float2*)(op1 + cc) = make_float2(oacc[nt][2] * inv1, oacc[nt][3] * inv1);
    }
}

// ---------------- launcher ----------------
extern "C" void kernel_launch(void* const* d_in, const int* in_sizes, int n_in,
                              void* d_out, int out_size) {
    const float* hidden = (const float*)d_in[0];
    const float* cosb   = (const float*)d_in[1];
    const float* sinb   = (const float*)d_in[2];
    const float* wqkv   = (const float*)d_in[3];
    const float* wo     = (const float*)d_in[4];

    float* qkv = nullptr;
    float* attn = nullptr;
    cudaGetSymbolAddress((void**)&qkv, g_qkv);
    cudaGetSymbolAddress((void**)&attn, g_attn);
    cudaFuncSetAttribute(flash_kernel, cudaFuncAttributeMaxDynamicSharedMemorySize, FA_SMEM_BYTES);

    // 1) QKV projection: [4096,2048] x [6144,2048]^T
    gemm_nt<<<dim3(NQKV / 128, (BB * SS) / 128), 256>>>(hidden, wqkv, qkv, BB * SS, NQKV, HIDD);

    // 2) RoPE + split + transpose (12,582,912 pairs = 49152 * 256 exactly)
    rope_split_kernel<<<49152, 256>>>(cosb, sinb);

    // 3) Attention
    flash_kernel<<<dim3(SS / 128, BB * HH), 256, FA_SMEM_BYTES>>>();

    // 4) Output projection: [4096,2048] x [2048,2048]^T -> d_out
    gemm_nt<<<dim3(HIDD / 128, (BB * SS) / 128), 256>>>(attn, wo, (float*)d_out, BB * SS, HIDD, HIDD);
}